// round 12
// baseline (speedup 1.0000x reference)
#include <cuda_runtime.h>
#include <math.h>
#include <stdint.h>

// Problem constants
#define TT   131072   // tokens
#define D_IN 256      // input dim
#define HH   128      // per-direction hidden
#define G4   512      // 4*HH gate rows
#define HID  256      // bidirectional hidden
#define TAGS 10
#define NSEG 1024

// Scratch (device globals — no allocation allowed in kernel_launch)
__device__ float g_pre[2][TT][G4];   // pre-activations per direction (original token order)
__device__ float g_hs[TT][HID];      // [hf | hb] concatenated
__device__ float g_att[TT];          // attention logits

// Fast activations: __expf (EX2) + __fdividef (~2 ulp). Inf-safe saturation.
__device__ __forceinline__ float fsigmoid(float x) {
    return __fdividef(1.0f, 1.0f + __expf(-x));
}
__device__ __forceinline__ float ftanh(float x) {
    return 1.0f - __fdividef(2.0f, __expf(2.0f * x) + 1.0f);
}
// Accurate tanh for the (non-recurrent) attention path
__device__ __forceinline__ float tanh_acc(float x) {
    return 1.0f - 2.0f / (__expf(2.0f * x) + 1.0f);
}

// Packed dual-FMA (Blackwell f32x2). acc.{lo,hi} += a.{lo,hi} * b.{lo,hi}
__device__ __forceinline__ void ffma2(unsigned long long& acc,
                                      unsigned long long a,
                                      unsigned long long b) {
    asm("fma.rn.f32x2 %0, %1, %2, %0;" : "+l"(acc) : "l"(a), "l"(b));
}

__device__ __forceinline__ uint32_t smem_u32(const void* p) {
    uint32_t a;
    asm("{ .reg .u64 t; cvta.to.shared.u64 t, %1; cvt.u32.u64 %0, t; }"
        : "=r"(a) : "l"(p));
    return a;
}

// Cluster-scope acquire wait on a local mbarrier (spin on try_wait.parity)
__device__ __forceinline__ void mbar_wait_cluster(uint32_t addr, uint32_t parity) {
    uint32_t done;
    asm volatile(
        "{\n\t.reg .pred p;\n\t"
        "mbarrier.try_wait.parity.acquire.cluster.shared::cta.b64 p, [%1], %2;\n\t"
        "selp.b32 %0, 1, 0, p;\n\t}"
        : "=r"(done) : "r"(addr), "r"(parity) : "memory");
    if (!done) {
        asm volatile(
            "{\n\t.reg .pred P1;\n\t"
            "WL_%=:\n\t"
            "mbarrier.try_wait.parity.acquire.cluster.shared::cta.b64 P1, [%0], %1, 0x989680;\n\t"
            "@P1 bra.uni WD_%=;\n\t"
            "bra.uni WL_%=;\n\t"
            "WD_%=:\n\t}"
            :: "r"(addr), "r"(parity) : "memory");
    }
}

// ---------------------------------------------------------------------------
// Kernel A: pre[dir][t][g] = x[t] . w_ih[g] + b_ih[g] + b_hh[g]
// ---------------------------------------------------------------------------
__global__ __launch_bounds__(256) void gemm_pre_kernel(
    const float* __restrict__ x,
    const float* __restrict__ wf, const float* __restrict__ bif, const float* __restrict__ bhf,
    const float* __restrict__ wb, const float* __restrict__ bib, const float* __restrict__ bhb)
{
    int dir = blockIdx.z;
    const float* w  = dir ? wb  : wf;
    const float* b1 = dir ? bib : bif;
    const float* b2 = dir ? bhb : bhf;
    float* out = &g_pre[dir][0][0];

    int tok0 = blockIdx.x * 64;
    int g0   = blockIdx.y * 64;

    __shared__ float xs[16][64];
    __shared__ float wsm[16][64];

    int tid = threadIdx.x;
    int tx = tid & 15;
    int ty = tid >> 4;

    float acc[4][4];
#pragma unroll
    for (int i = 0; i < 4; i++)
#pragma unroll
        for (int j = 0; j < 4; j++) acc[i][j] = 0.f;

    int lr = tid >> 2;
    int lc = (tid & 3) * 4;

    for (int kk = 0; kk < D_IN; kk += 16) {
        float4 xv = *(const float4*)(x + (size_t)(tok0 + lr) * D_IN + kk + lc);
        float4 wv = *(const float4*)(w + (size_t)(g0  + lr) * D_IN + kk + lc);
        xs[lc + 0][lr] = xv.x; xs[lc + 1][lr] = xv.y; xs[lc + 2][lr] = xv.z; xs[lc + 3][lr] = xv.w;
        wsm[lc + 0][lr] = wv.x; wsm[lc + 1][lr] = wv.y; wsm[lc + 2][lr] = wv.z; wsm[lc + 3][lr] = wv.w;
        __syncthreads();
#pragma unroll
        for (int k = 0; k < 16; k++) {
            float4 a = *(const float4*)&xs[k][ty * 4];
            float4 b = *(const float4*)&wsm[k][tx * 4];
            float av[4] = {a.x, a.y, a.z, a.w};
            float bv[4] = {b.x, b.y, b.z, b.w};
#pragma unroll
            for (int i = 0; i < 4; i++)
#pragma unroll
                for (int j = 0; j < 4; j++)
                    acc[i][j] = fmaf(av[i], bv[j], acc[i][j]);
        }
        __syncthreads();
    }

    int g = g0 + tx * 4;
    float bb0 = b1[g + 0] + b2[g + 0];
    float bb1 = b1[g + 1] + b2[g + 1];
    float bb2 = b1[g + 2] + b2[g + 2];
    float bb3 = b1[g + 3] + b2[g + 3];
#pragma unroll
    for (int i = 0; i < 4; i++) {
        int tok = tok0 + ty * 4 + i;
        float4 o;
        o.x = acc[i][0] + bb0;
        o.y = acc[i][1] + bb1;
        o.z = acc[i][2] + bb2;
        o.w = acc[i][3] + bb3;
        *(float4*)(out + (size_t)tok * G4 + g) = o;
    }
}

// ---------------------------------------------------------------------------
// Kernel B: BOTH LSTM directions interleaved in ONE 4-CTA cluster (gate split).
//
// CTA rank q owns gate q (rows q*128..q*128+127) of BOTH directions.
// 256 threads: thread t handles row j=t>>1, column-half hc=t&1 (64 cols) of
// its gate row in dir F(orward) and dir B(ackward): 2 x 32 u64 weight regs.
// Per iteration u (advances BOTH directions by one step):
//   1 matvec B(u)  [h_B local]; shfl-combine; even threads store gate sum
//     to local gB[u&1][rank][j] + 3 peers (st.shared::cluster)
//   2 wait mbF[u&1]  (acquire; F gate sums of step u — signal sent last iter,
//     flight hidden under this iter's B matvec)
//   3 act F(u) -> c_F,h_F (even threads, all CTAs bitwise-identical); g_hs
//   4 BAR1  (publishes: B gate stores issued + h_F)
//   5 t0: 3x mbarrier.arrive.release.cluster -> peers' mbB[u&1]
//     (R9-validated: release after BAR publishes all threads' stores)
//   6 matvec F(u+1) [h_F from step 3]; store gF[(u+1)&1][rank][j] local+peers
//   7 wait mbB[u&1]  (flight hidden under matvec F)
//   8 act B(u) -> c_B,h_B; g_hs
//   9 BAR2  (publishes: F gate stores + h_B)
//  10 t0: 3x arrive -> peers' mbF[(u+1)&1]
// Orderings verified: WAR on gB[u&1] (my iter-u store po-after wait mbB[(u-1)&1]
// at iter u-1, needing peers' arrives po-after their act B(u-2) reads); WAR on
// gF[(u+1)&1] (store po-after wait mbF[u&1], needing peers' arrives po-after
// their act F(u-1) reads); phase overrun impossible (arrive for phase k+2 is
// po-after wait of phase k+1, which needs all peers past phase k).
// mbarriers count=3 (3 peer arrives), double-buffered, re-inited per launch.
// ---------------------------------------------------------------------------
__global__ __launch_bounds__(256, 1) __cluster_dims__(4, 1, 1)
void lstm_kernel(
    const float* __restrict__ w_hh_f, const float* __restrict__ w_hh_b,
    const float* __restrict__ h0, const float* __restrict__ c0)
{
    __shared__ __align__(16) float hF[HH];
    __shared__ __align__(16) float hB[HH];
    __shared__ __align__(16) float gF[2][4][HH];
    __shared__ __align__(16) float gB[2][4][HH];
    __shared__ __align__(8) unsigned long long mb[4];  // mbF[0],mbF[1],mbB[0],mbB[1]

    uint32_t rank = blockIdx.x;          // gate index
    int t  = threadIdx.x;
    int j  = t >> 1;                      // row within gate == h index
    int hc = t & 1;                       // column half
    int r  = (int)rank * HH + j;          // global gate row

    const ulonglong2* WrF = (const ulonglong2*)(w_hh_f + (size_t)r * HH + hc * 64);
    const ulonglong2* WrB = (const ulonglong2*)(w_hh_b + (size_t)r * HH + hc * 64);

    unsigned long long wpF[32], wpB[32];
#pragma unroll
    for (int i = 0; i < 16; i++) {
        ulonglong2 vF = WrF[i]; wpF[2 * i] = vF.x; wpF[2 * i + 1] = vF.y;
        ulonglong2 vB = WrB[i]; wpB[2 * i] = vB.x; wpB[2 * i + 1] = vB.y;
    }

    if (t == 0) {
        uint32_t mba = smem_u32(&mb[0]);
#pragma unroll
        for (int k = 0; k < 4; k++)
            asm volatile("mbarrier.init.shared.b64 [%0], %1;" :: "r"(mba + k * 8), "r"(3u) : "memory");
    }
    if (t < HH) { hF[t] = h0[t]; hB[t] = h0[HH + t]; }
    float c_F = 0.f, c_B = 0.f;
    if (hc == 0) { c_F = c0[j]; c_B = c0[HH + j]; }
    __syncthreads();
    asm volatile("barrier.cluster.arrive.aligned;" ::: "memory");
    asm volatile("barrier.cluster.wait.aligned;" ::: "memory");

    // Peer addresses (3 peers), computed once
    uint32_t l_gF = smem_u32(&gF[0][0][0]);
    uint32_t l_gB = smem_u32(&gB[0][0][0]);
    uint32_t l_mb = smem_u32(&mb[0]);
    uint32_t slot = (rank * HH + (uint32_t)j) * 4u;     // even threads' store slot
    uint32_t pgF[3], pgB[3], pmb[3];
    {
        int n = 0;
#pragma unroll
        for (uint32_t q = 0; q < 4; q++) {
            if (q != rank) {
                uint32_t bF, bB, bM;
                asm("mapa.shared::cluster.u32 %0, %1, %2;" : "=r"(bF) : "r"(l_gF), "r"(q));
                asm("mapa.shared::cluster.u32 %0, %1, %2;" : "=r"(bB) : "r"(l_gB), "r"(q));
                asm("mapa.shared::cluster.u32 %0, %1, %2;" : "=r"(bM) : "r"(l_mb), "r"(q));
                pgF[n] = bF + slot; pgB[n] = bB + slot; pmb[n] = bM; n++;
            }
        }
    }

    const float* PF = &g_pre[0][0][0];
    const float* PB = &g_pre[1][0][0];

    // pre prefetch (even threads only carry pre)
    float pfF0 = 0.f, pfF1 = 0.f, pfB0 = 0.f, pfB1 = 0.f;
    if (hc == 0) {
        pfB0 = __ldg(PB + (size_t)(TT - 1) * G4 + r);
        pfB1 = __ldg(PB + (size_t)(TT - 2) * G4 + r);
    }

    // ---- per-direction half-row matvec ----
#define MATVEC(hbuf, wp, pre, vout)                                            \
    {                                                                          \
        const ulonglong2* hp = (const ulonglong2*)(&hbuf[0] + hc * 64);        \
        unsigned long long a0, a1;                                             \
        asm("mov.b64 %0, {%1,%2};" : "=l"(a0) : "f"(pre), "f"(0.0f));          \
        asm("mov.b64 %0, {%1,%2};" : "=l"(a1) : "f"(0.0f), "f"(0.0f));         \
        _Pragma("unroll")                                                      \
        for (int i = 0; i < 16; i++) {                                         \
            ulonglong2 hv = hp[i];                                             \
            ffma2(a0, wp[2 * i],     hv.x);                                    \
            ffma2(a1, wp[2 * i + 1], hv.y);                                    \
        }                                                                      \
        float s0, s1, s2, s3;                                                  \
        asm("mov.b64 {%0,%1}, %2;" : "=f"(s0), "=f"(s1) : "l"(a0));            \
        asm("mov.b64 {%0,%1}, %2;" : "=f"(s2), "=f"(s3) : "l"(a1));            \
        float vv = (s0 + s1) + (s2 + s3);                                      \
        vout = vv + __shfl_xor_sync(0xffffffffu, vv, 1);                       \
    }

    // Prologue: matvec F(0), store, BAR, signal mbF[0]
    {
        float preF;
        if (hc == 0) {
            preF = __ldg(PF + (size_t)0 * G4 + r);
            pfF0 = __ldg(PF + (size_t)1 * G4 + r);
            pfF1 = __ldg(PF + (size_t)2 * G4 + r);
        } else preF = 0.f;
        float v;
        MATVEC(hF, wpF, preF, v);
        if (hc == 0) {
            gF[0][rank][j] = v;
            asm volatile("st.shared::cluster.f32 [%0], %1;" :: "r"(pgF[0]), "f"(v) : "memory");
            asm volatile("st.shared::cluster.f32 [%0], %1;" :: "r"(pgF[1]), "f"(v) : "memory");
            asm volatile("st.shared::cluster.f32 [%0], %1;" :: "r"(pgF[2]), "f"(v) : "memory");
        }
        __syncthreads();
        if (t == 0) {
#pragma unroll
            for (int k = 0; k < 3; k++)
                asm volatile("mbarrier.arrive.release.cluster.shared::cluster.b64 _, [%0];"
                             :: "r"(pmb[k] + 0u) : "memory");
        }
    }

    uint32_t phF0 = 0, phF1 = 0, phB0 = 0, phB1 = 0;

    for (int u = 0; u < TT; u++) {
        const int buf  = u & 1;
        const int nbuf = buf ^ 1;
        const uint32_t bo  = (uint32_t)(buf * 4 * HH * 4);
        const uint32_t nbo = (uint32_t)(nbuf * 4 * HH * 4);

        // 1. matvec B(u) + store gate sums
        {
            float v;
            MATVEC(hB, wpB, pfB0, v);
            pfB0 = pfB1;
            if (hc == 0) {
                int rr = TT - 1 - (u + 2);
                rr = rr < 0 ? 0 : rr;
                pfB1 = __ldg(PB + (size_t)rr * G4 + r);
                gB[buf][rank][j] = v;
                asm volatile("st.shared::cluster.f32 [%0], %1;" :: "r"(pgB[0] + bo), "f"(v) : "memory");
                asm volatile("st.shared::cluster.f32 [%0], %1;" :: "r"(pgB[1] + bo), "f"(v) : "memory");
                asm volatile("st.shared::cluster.f32 [%0], %1;" :: "r"(pgB[2] + bo), "f"(v) : "memory");
            }
        }

        // 2. wait F gate sums (step u)
        if (buf == 0) { mbar_wait_cluster(l_mb + 0, phF0); phF0 ^= 1u; }
        else          { mbar_wait_cluster(l_mb + 8, phF1); phF1 ^= 1u; }

        // 3. act F(u)
        if (hc == 0) {
            float iv = fsigmoid(gF[buf][0][j]);
            float fv = fsigmoid(gF[buf][1][j]);
            float gv = ftanh(gF[buf][2][j]);
            float ov = fsigmoid(gF[buf][3][j]);
            c_F = fv * c_F + iv * gv;
            float hv = ov * ftanh(c_F);
            hF[j] = hv;
            if (rank == 0) g_hs[u][j] = hv;
        }
        __syncthreads();   // BAR1: B gate stores + hF published CTA-locally

        // 5. signal B(u)
        if (t == 0) {
#pragma unroll
            for (int k = 0; k < 3; k++)
                asm volatile("mbarrier.arrive.release.cluster.shared::cluster.b64 _, [%0];"
                             :: "r"(pmb[k] + 16u + (uint32_t)(buf * 8)) : "memory");
        }

        // 6. matvec F(u+1) + store gate sums
        {
            float v;
            MATVEC(hF, wpF, pfF0, v);
            pfF0 = pfF1;
            if (hc == 0) {
                int rr = u + 3;
                rr = rr >= TT ? TT - 1 : rr;
                pfF1 = __ldg(PF + (size_t)rr * G4 + r);
                gF[nbuf][rank][j] = v;
                asm volatile("st.shared::cluster.f32 [%0], %1;" :: "r"(pgF[0] + nbo), "f"(v) : "memory");
                asm volatile("st.shared::cluster.f32 [%0], %1;" :: "r"(pgF[1] + nbo), "f"(v) : "memory");
                asm volatile("st.shared::cluster.f32 [%0], %1;" :: "r"(pgF[2] + nbo), "f"(v) : "memory");
            }
        }

        // 7. wait B gate sums (step u)
        if (buf == 0) { mbar_wait_cluster(l_mb + 16, phB0); phB0 ^= 1u; }
        else          { mbar_wait_cluster(l_mb + 24, phB1); phB1 ^= 1u; }

        // 8. act B(u)
        if (hc == 0) {
            float iv = fsigmoid(gB[buf][0][j]);
            float fv = fsigmoid(gB[buf][1][j]);
            float gv = ftanh(gB[buf][2][j]);
            float ov = fsigmoid(gB[buf][3][j]);
            c_B = fv * c_B + iv * gv;
            float hv = ov * ftanh(c_B);
            hB[j] = hv;
            if (rank == 0) g_hs[TT - 1 - u][HH + j] = hv;
        }
        __syncthreads();   // BAR2: F gate stores + hB published CTA-locally

        // 10. signal F(u+1)
        if (t == 0) {
#pragma unroll
            for (int k = 0; k < 3; k++)
                asm volatile("mbarrier.arrive.release.cluster.shared::cluster.b64 _, [%0];"
                             :: "r"(pmb[k] + (uint32_t)(nbuf * 8)) : "memory");
        }
    }

    // no CTA may exit while peers can still touch its smem
    asm volatile("barrier.cluster.arrive.aligned;" ::: "memory");
    asm volatile("barrier.cluster.wait.aligned;" ::: "memory");
#undef MATVEC
}

// ---------------------------------------------------------------------------
// Kernel C: att[t] = sum_d tanh( (x @ w_omega)[t,d] ) * u_omega[d]
// ---------------------------------------------------------------------------
#define ATTN_SMEM ((64 * HID + 16 * 257) * 4)

__global__ __launch_bounds__(256) void attn_kernel(
    const float* __restrict__ w_omega, const float* __restrict__ u_omega)
{
    extern __shared__ float smc[];
    float* xs  = smc;
    float* red = smc + 64 * HID;

    int tid  = threadIdx.x;
    int tok0 = blockIdx.x * 64;

    const float4* src = (const float4*)&g_hs[tok0][0];
    float4* dst = (float4*)xs;
    for (int idx = tid; idx < 64 * HID / 4; idx += 256) dst[idx] = src[idx];
    __syncthreads();

    float uo = u_omega[tid];

    for (int c = 0; c < 4; c++) {
        float acc[16];
#pragma unroll
        for (int t = 0; t < 16; t++) acc[t] = 0.f;
        const float* xbase = xs + (c * 16) * HID;

        for (int k = 0; k < HID; k += 4) {
            float w0 = __ldg(w_omega + (k + 0) * HID + tid);
            float w1 = __ldg(w_omega + (k + 1) * HID + tid);
            float w2 = __ldg(w_omega + (k + 2) * HID + tid);
            float w3 = __ldg(w_omega + (k + 3) * HID + tid);
#pragma unroll
            for (int t = 0; t < 16; t++) {
                float4 xv = *(const float4*)(xbase + t * HID + k);
                acc[t] = fmaf(xv.x, w0,
                         fmaf(xv.y, w1,
                         fmaf(xv.z, w2,
                         fmaf(xv.w, w3, acc[t]))));
            }
        }
#pragma unroll
        for (int t = 0; t < 16; t++)
            red[t * 257 + tid] = tanh_acc(acc[t]) * uo;
        __syncthreads();
        if (tid < 16) {
            float s = 0.f;
            for (int jx = 0; jx < HID; jx++) s += red[tid * 257 + jx];
            g_att[tok0 + c * 16 + tid] = s;
        }
        __syncthreads();
    }
}

// ---------------------------------------------------------------------------
// Kernel D: per-segment softmax pooling + tag projection
// ---------------------------------------------------------------------------
__global__ __launch_bounds__(256) void seg_pool_kernel(
    const int* __restrict__ mask,
    const float* __restrict__ w_tag, const float* __restrict__ b_tag,
    float* __restrict__ out)
{
    int s = blockIdx.x;
    int tid = threadIdx.x;
    int lo = (s == 0) ? 0 : mask[s - 1];
    int hi = (s == NSEG - 1) ? TT : mask[s];

    if (lo >= hi) {
        if (tid < TAGS) out[s * TAGS + tid] = b_tag[tid];
        return;
    }

    __shared__ float red[256];
    __shared__ float e_sm[256];
    __shared__ float ctx[256];

    float m = -3.4e38f;
    for (int i = lo + tid; i < hi; i += 256) m = fmaxf(m, g_att[i]);
    red[tid] = m; __syncthreads();
    for (int w = 128; w > 0; w >>= 1) {
        if (tid < w) red[tid] = fmaxf(red[tid], red[tid + w]);
        __syncthreads();
    }
    m = red[0]; __syncthreads();

    float z = 0.f;
    for (int i = lo + tid; i < hi; i += 256) z += __expf(g_att[i] - m);
    red[tid] = z; __syncthreads();
    for (int w = 128; w > 0; w >>= 1) {
        if (tid < w) red[tid] += red[tid + w];
        __syncthreads();
    }
    z = red[0]; __syncthreads();

    float acc = 0.f;
    for (int base = lo; base < hi; base += 256) {
        int i = base + tid;
        e_sm[tid] = (i < hi) ? __expf(g_att[i] - m) : 0.f;
        __syncthreads();
        int n = min(256, hi - base);
        for (int jx = 0; jx < n; jx++)
            acc = fmaf(g_hs[base + jx][tid], e_sm[jx], acc);
        __syncthreads();
    }
    ctx[tid] = acc / z;
    __syncthreads();

    if (tid < TAGS) {
        float rr = b_tag[tid];
        for (int d = 0; d < HID; d++) rr = fmaf(ctx[d], w_tag[tid * HID + d], rr);
        out[s * TAGS + tid] = rr;
    }
}

// ---------------------------------------------------------------------------
extern "C" void kernel_launch(void* const* d_in, const int* in_sizes, int n_in,
                              void* d_out, int out_size)
{
    const float* sentence = (const float*)d_in[0];
    const float* h0       = (const float*)d_in[1];
    const float* c0       = (const float*)d_in[2];
    const float* w_ih_f   = (const float*)d_in[3];
    const float* w_hh_f   = (const float*)d_in[4];
    const float* b_ih_f   = (const float*)d_in[5];
    const float* b_hh_f   = (const float*)d_in[6];
    const float* w_ih_b   = (const float*)d_in[7];
    const float* w_hh_b   = (const float*)d_in[8];
    const float* b_ih_b   = (const float*)d_in[9];
    const float* b_hh_b   = (const float*)d_in[10];
    const float* w_omega  = (const float*)d_in[11];
    const float* u_omega  = (const float*)d_in[12];
    const float* w_tag    = (const float*)d_in[13];
    const float* b_tag    = (const float*)d_in[14];
    const int*   doc_mask = (const int*)d_in[15];
    float* out = (float*)d_out;

    cudaFuncSetAttribute(attn_kernel, cudaFuncAttributeMaxDynamicSharedMemorySize, ATTN_SMEM);

    dim3 ggrid(TT / 64, G4 / 64, 2);
    gemm_pre_kernel<<<ggrid, 256>>>(sentence, w_ih_f, b_ih_f, b_hh_f,
                                    w_ih_b, b_ih_b, b_hh_b);
    lstm_kernel<<<4, 256>>>(w_hh_f, w_hh_b, h0, c0);
    attn_kernel<<<TT / 64, 256, ATTN_SMEM>>>(w_omega, u_omega);
    seg_pool_kernel<<<NSEG, 256>>>(doc_mask, w_tag, b_tag, out);
}

// round 14
// speedup vs baseline: 1.5764x; 1.5764x over previous
#include <cuda_runtime.h>
#include <math.h>
#include <stdint.h>

// Problem constants
#define TT   131072   // tokens
#define D_IN 256      // input dim
#define HH   128      // per-direction hidden
#define G4   512      // 4*HH gate rows
#define HID  256      // bidirectional hidden
#define TAGS 10
#define NSEG 1024

// Scratch (device globals — no allocation allowed in kernel_launch)
__device__ float g_pre[2][TT][G4];   // pre-activations per direction (original token order)
__device__ float g_hs[TT][HID];      // [hf | hb] concatenated
__device__ float g_att[TT];          // attention logits

// Fast activations: __expf (EX2) + __fdividef (~2 ulp). Inf-safe saturation.
__device__ __forceinline__ float fsigmoid(float x) {
    return __fdividef(1.0f, 1.0f + __expf(-x));
}
__device__ __forceinline__ float ftanh(float x) {
    return 1.0f - __fdividef(2.0f, __expf(2.0f * x) + 1.0f);
}
// Accurate tanh for the (non-recurrent) attention path
__device__ __forceinline__ float tanh_acc(float x) {
    return 1.0f - 2.0f / (__expf(2.0f * x) + 1.0f);
}

// Packed dual-FMA (Blackwell f32x2). acc.{lo,hi} += a.{lo,hi} * b.{lo,hi}
__device__ __forceinline__ void ffma2(unsigned long long& acc,
                                      unsigned long long a,
                                      unsigned long long b) {
    asm("fma.rn.f32x2 %0, %1, %2, %0;" : "+l"(acc) : "l"(a), "l"(b));
}

__device__ __forceinline__ uint32_t smem_u32(const void* p) {
    uint32_t a;
    asm("{ .reg .u64 t; cvta.to.shared.u64 t, %1; cvt.u32.u64 %0, t; }"
        : "=r"(a) : "l"(p));
    return a;
}

#define CB_ARRIVE() asm volatile("barrier.cluster.arrive.aligned;" ::: "memory")
#define CB_WAIT()   asm volatile("barrier.cluster.wait.aligned;" ::: "memory")

// ---------------------------------------------------------------------------
// Kernel A: pre[dir][t][g] = x[t] . w_ih[g] + b_ih[g] + b_hh[g]
// ---------------------------------------------------------------------------
__global__ __launch_bounds__(256) void gemm_pre_kernel(
    const float* __restrict__ x,
    const float* __restrict__ wf, const float* __restrict__ bif, const float* __restrict__ bhf,
    const float* __restrict__ wb, const float* __restrict__ bib, const float* __restrict__ bhb)
{
    int dir = blockIdx.z;
    const float* w  = dir ? wb  : wf;
    const float* b1 = dir ? bib : bif;
    const float* b2 = dir ? bhb : bhf;
    float* out = &g_pre[dir][0][0];

    int tok0 = blockIdx.x * 64;
    int g0   = blockIdx.y * 64;

    __shared__ float xs[16][64];
    __shared__ float wsm[16][64];

    int tid = threadIdx.x;
    int tx = tid & 15;
    int ty = tid >> 4;

    float acc[4][4];
#pragma unroll
    for (int i = 0; i < 4; i++)
#pragma unroll
        for (int j = 0; j < 4; j++) acc[i][j] = 0.f;

    int lr = tid >> 2;
    int lc = (tid & 3) * 4;

    for (int kk = 0; kk < D_IN; kk += 16) {
        float4 xv = *(const float4*)(x + (size_t)(tok0 + lr) * D_IN + kk + lc);
        float4 wv = *(const float4*)(w + (size_t)(g0  + lr) * D_IN + kk + lc);
        xs[lc + 0][lr] = xv.x; xs[lc + 1][lr] = xv.y; xs[lc + 2][lr] = xv.z; xs[lc + 3][lr] = xv.w;
        wsm[lc + 0][lr] = wv.x; wsm[lc + 1][lr] = wv.y; wsm[lc + 2][lr] = wv.z; wsm[lc + 3][lr] = wv.w;
        __syncthreads();
#pragma unroll
        for (int k = 0; k < 16; k++) {
            float4 a = *(const float4*)&xs[k][ty * 4];
            float4 b = *(const float4*)&wsm[k][tx * 4];
            float av[4] = {a.x, a.y, a.z, a.w};
            float bv[4] = {b.x, b.y, b.z, b.w};
#pragma unroll
            for (int i = 0; i < 4; i++)
#pragma unroll
                for (int j = 0; j < 4; j++)
                    acc[i][j] = fmaf(av[i], bv[j], acc[i][j]);
        }
        __syncthreads();
    }

    int g = g0 + tx * 4;
    float bb0 = b1[g + 0] + b2[g + 0];
    float bb1 = b1[g + 1] + b2[g + 1];
    float bb2 = b1[g + 2] + b2[g + 2];
    float bb3 = b1[g + 3] + b2[g + 3];
#pragma unroll
    for (int i = 0; i < 4; i++) {
        int tok = tok0 + ty * 4 + i;
        float4 o;
        o.x = acc[i][0] + bb0;
        o.y = acc[i][1] + bb1;
        o.z = acc[i][2] + bb2;
        o.w = acc[i][3] + bb3;
        *(float4*)(out + (size_t)tok * G4 + g) = o;
    }
}

// ---------------------------------------------------------------------------
// Kernel B: BOTH LSTM directions in ONE 4-CTA cluster, gate split, using the
// hardware cluster barrier in SPLIT arrive/wait form to hide rendezvous
// latency under the other direction's matvec. NO mbarriers (R12 lesson).
//
// CTA rank q owns gate q's 128 rows of both dirs; 256 threads: thread =
// (row j = t>>1, col-half hc = t&1); weights 2 x 32 u64 regs (~170 regs).
// Steady-state iteration u (advances F and B one step each):
//   [in flight: gF(u) exchange, arrived at end of prev iter]
//   1 matvec B(u) from hB; even threads store gB[u&1] local + 3 peers
//   2 CB_WAIT            -> gF(u) visible (release-by-arrive / acquire-by-wait)
//   3 act F(u) (even)    -> hF, g_hs ; __syncthreads
//   4 CB_ARRIVE          -> releases this thread's gB(u) stores
//   5 matvec F(u+1) from hF; even store gF[(u+1)&1] local + 3 peers
//   6 CB_WAIT            -> gB(u) visible
//   7 act B(u) (even)    -> hB, g_hs ; __syncthreads
//   8 CB_ARRIVE          -> releases gF(u+1) stores
// Arrive/wait strictly alternate per thread (init A/W, prologue A, loop
// (W A W A) x TT, final W, exit A/W) -> generations stay matched.
// WAR on gF/gB: double-buffered; store to a buffer at iter u+2 is po-after
// the wait whose matching arrives are po-after peers' reads at iter u.
// h single-buffered: local act writes vs local matvec reads ordered by the
// cluster barrier (all 256 local threads participate) + __syncthreads.
// ---------------------------------------------------------------------------
__global__ __launch_bounds__(256, 1) __cluster_dims__(4, 1, 1)
void lstm_kernel(
    const float* __restrict__ w_hh_f, const float* __restrict__ w_hh_b,
    const float* __restrict__ h0, const float* __restrict__ c0)
{
    __shared__ __align__(16) float hF[HH];
    __shared__ __align__(16) float hB[HH];
    __shared__ __align__(16) float gF[2][4][HH];
    __shared__ __align__(16) float gB[2][4][HH];

    uint32_t rank = blockIdx.x;          // gate index
    int t  = threadIdx.x;
    int j  = t >> 1;                      // row within gate == h index
    int hc = t & 1;                       // column half
    int r  = (int)rank * HH + j;          // global gate row

    const ulonglong2* WrF = (const ulonglong2*)(w_hh_f + (size_t)r * HH + hc * 64);
    const ulonglong2* WrB = (const ulonglong2*)(w_hh_b + (size_t)r * HH + hc * 64);

    unsigned long long wpF[32], wpB[32];
#pragma unroll
    for (int i = 0; i < 16; i++) {
        ulonglong2 vF = WrF[i]; wpF[2 * i] = vF.x; wpF[2 * i + 1] = vF.y;
        ulonglong2 vB = WrB[i]; wpB[2 * i] = vB.x; wpB[2 * i + 1] = vB.y;
    }

    if (t < HH) { hF[t] = h0[t]; hB[t] = h0[HH + t]; }
    float c_F = 0.f, c_B = 0.f;
    if (hc == 0) { c_F = c0[j]; c_B = c0[HH + j]; }
    __syncthreads();
    CB_ARRIVE(); CB_WAIT();   // gen 0: smem init + residency

    // Peer gbuf addresses (3 peers), computed once
    uint32_t l_gF = smem_u32(&gF[0][0][0]);
    uint32_t l_gB = smem_u32(&gB[0][0][0]);
    uint32_t slot = (rank * HH + (uint32_t)j) * 4u;     // even threads' slot
    uint32_t pgF[3], pgB[3];
    {
        int n = 0;
#pragma unroll
        for (uint32_t q = 0; q < 4; q++) {
            if (q != rank) {
                uint32_t bF, bB;
                asm("mapa.shared::cluster.u32 %0, %1, %2;" : "=r"(bF) : "r"(l_gF), "r"(q));
                asm("mapa.shared::cluster.u32 %0, %1, %2;" : "=r"(bB) : "r"(l_gB), "r"(q));
                pgF[n] = bF + slot; pgB[n] = bB + slot; n++;
            }
        }
    }

    const float* PF = &g_pre[0][0][0];
    const float* PB = &g_pre[1][0][0];

    float pfF0 = 0.f, pfF1 = 0.f, pfB0 = 0.f, pfB1 = 0.f;
    if (hc == 0) {
        pfB0 = __ldg(PB + (size_t)(TT - 1) * G4 + r);
        pfB1 = __ldg(PB + (size_t)(TT - 2) * G4 + r);
    }

#define MATVEC(hbuf, wp, pre, vout)                                            \
    {                                                                          \
        const ulonglong2* hp = (const ulonglong2*)(&hbuf[0] + hc * 64);        \
        unsigned long long a0, a1;                                             \
        asm("mov.b64 %0, {%1,%2};" : "=l"(a0) : "f"(pre), "f"(0.0f));          \
        asm("mov.b64 %0, {%1,%2};" : "=l"(a1) : "f"(0.0f), "f"(0.0f));         \
        _Pragma("unroll")                                                      \
        for (int i = 0; i < 16; i++) {                                         \
            ulonglong2 hv = hp[i];                                             \
            ffma2(a0, wp[2 * i],     hv.x);                                    \
            ffma2(a1, wp[2 * i + 1], hv.y);                                    \
        }                                                                      \
        float s0, s1, s2, s3;                                                  \
        asm("mov.b64 {%0,%1}, %2;" : "=f"(s0), "=f"(s1) : "l"(a0));            \
        asm("mov.b64 {%0,%1}, %2;" : "=f"(s2), "=f"(s3) : "l"(a1));            \
        float vv = (s0 + s1) + (s2 + s3);                                      \
        vout = vv + __shfl_xor_sync(0xffffffffu, vv, 1);                       \
    }

    // Prologue: matvec F(0), store gF[0], ARRIVE (gen 1; exchange in flight)
    {
        float preF;
        if (hc == 0) {
            preF  = __ldg(PF + (size_t)0 * G4 + r);
            pfF0  = __ldg(PF + (size_t)1 * G4 + r);
            pfF1  = __ldg(PF + (size_t)2 * G4 + r);
        } else preF = 0.f;
        float v;
        MATVEC(hF, wpF, preF, v);
        if (hc == 0) {
            gF[0][rank][j] = v;
            asm volatile("st.shared::cluster.f32 [%0], %1;" :: "r"(pgF[0]), "f"(v) : "memory");
            asm volatile("st.shared::cluster.f32 [%0], %1;" :: "r"(pgF[1]), "f"(v) : "memory");
            asm volatile("st.shared::cluster.f32 [%0], %1;" :: "r"(pgF[2]), "f"(v) : "memory");
        }
        CB_ARRIVE();
    }

    for (int u = 0; u < TT; u++) {
        const int buf  = u & 1;
        const int nbuf = buf ^ 1;
        const uint32_t bo  = (uint32_t)(buf * 4 * HH * 4);
        const uint32_t nbo = (uint32_t)(nbuf * 4 * HH * 4);

        // 1. matvec B(u) + store (overlaps in-flight gF(u) rendezvous)
        {
            float v;
            MATVEC(hB, wpB, pfB0, v);
            pfB0 = pfB1;
            if (hc == 0) {
                int rr = TT - 1 - (u + 2);
                rr = rr < 0 ? 0 : rr;
                pfB1 = __ldg(PB + (size_t)rr * G4 + r);
                gB[buf][rank][j] = v;
                asm volatile("st.shared::cluster.f32 [%0], %1;" :: "r"(pgB[0] + bo), "f"(v) : "memory");
                asm volatile("st.shared::cluster.f32 [%0], %1;" :: "r"(pgB[1] + bo), "f"(v) : "memory");
                asm volatile("st.shared::cluster.f32 [%0], %1;" :: "r"(pgB[2] + bo), "f"(v) : "memory");
            }
        }

        // 2. gF(u) ready
        CB_WAIT();

        // 3. act F(u)
        if (hc == 0) {
            float iv = fsigmoid(gF[buf][0][j]);
            float fv = fsigmoid(gF[buf][1][j]);
            float gv = ftanh(gF[buf][2][j]);
            float ov = fsigmoid(gF[buf][3][j]);
            c_F = fv * c_F + iv * gv;
            float hv = ov * ftanh(c_F);
            hF[j] = hv;
            if (rank == 0) g_hs[u][j] = hv;
        }
        __syncthreads();

        // 4. release gB(u) stores; gB rendezvous in flight
        CB_ARRIVE();

        // 5. matvec F(u+1) + store (overlaps gB(u) rendezvous)
        {
            float v;
            MATVEC(hF, wpF, pfF0, v);
            pfF0 = pfF1;
            if (hc == 0) {
                int rr = u + 3;
                rr = rr >= TT ? TT - 1 : rr;
                pfF1 = __ldg(PF + (size_t)rr * G4 + r);
                gF[nbuf][rank][j] = v;
                asm volatile("st.shared::cluster.f32 [%0], %1;" :: "r"(pgF[0] + nbo), "f"(v) : "memory");
                asm volatile("st.shared::cluster.f32 [%0], %1;" :: "r"(pgF[1] + nbo), "f"(v) : "memory");
                asm volatile("st.shared::cluster.f32 [%0], %1;" :: "r"(pgF[2] + nbo), "f"(v) : "memory");
            }
        }

        // 6. gB(u) ready
        CB_WAIT();

        // 7. act B(u)
        if (hc == 0) {
            float iv = fsigmoid(gB[buf][0][j]);
            float fv = fsigmoid(gB[buf][1][j]);
            float gv = ftanh(gB[buf][2][j]);
            float ov = fsigmoid(gB[buf][3][j]);
            c_B = fv * c_B + iv * gv;
            float hv = ov * ftanh(c_B);
            hB[j] = hv;
            if (rank == 0) g_hs[TT - 1 - u][HH + j] = hv;
        }
        __syncthreads();

        // 8. release gF(u+1) stores
        CB_ARRIVE();
    }

    CB_WAIT();                 // match final arrive
    CB_ARRIVE(); CB_WAIT();    // exit residency barrier
#undef MATVEC
}

// ---------------------------------------------------------------------------
// Kernel C: att[t] = sum_d tanh( (x @ w_omega)[t,d] ) * u_omega[d]
// ---------------------------------------------------------------------------
#define ATTN_SMEM ((64 * HID + 16 * 257) * 4)

__global__ __launch_bounds__(256) void attn_kernel(
    const float* __restrict__ w_omega, const float* __restrict__ u_omega)
{
    extern __shared__ float smc[];
    float* xs  = smc;
    float* red = smc + 64 * HID;

    int tid  = threadIdx.x;
    int tok0 = blockIdx.x * 64;

    const float4* src = (const float4*)&g_hs[tok0][0];
    float4* dst = (float4*)xs;
    for (int idx = tid; idx < 64 * HID / 4; idx += 256) dst[idx] = src[idx];
    __syncthreads();

    float uo = u_omega[tid];

    for (int c = 0; c < 4; c++) {
        float acc[16];
#pragma unroll
        for (int t = 0; t < 16; t++) acc[t] = 0.f;
        const float* xbase = xs + (c * 16) * HID;

        for (int k = 0; k < HID; k += 4) {
            float w0 = __ldg(w_omega + (k + 0) * HID + tid);
            float w1 = __ldg(w_omega + (k + 1) * HID + tid);
            float w2 = __ldg(w_omega + (k + 2) * HID + tid);
            float w3 = __ldg(w_omega + (k + 3) * HID + tid);
#pragma unroll
            for (int t = 0; t < 16; t++) {
                float4 xv = *(const float4*)(xbase + t * HID + k);
                acc[t] = fmaf(xv.x, w0,
                         fmaf(xv.y, w1,
                         fmaf(xv.z, w2,
                         fmaf(xv.w, w3, acc[t]))));
            }
        }
#pragma unroll
        for (int t = 0; t < 16; t++)
            red[t * 257 + tid] = tanh_acc(acc[t]) * uo;
        __syncthreads();
        if (tid < 16) {
            float s = 0.f;
            for (int jx = 0; jx < HID; jx++) s += red[tid * 257 + jx];
            g_att[tok0 + c * 16 + tid] = s;
        }
        __syncthreads();
    }
}

// ---------------------------------------------------------------------------
// Kernel D: per-segment softmax pooling + tag projection
// ---------------------------------------------------------------------------
__global__ __launch_bounds__(256) void seg_pool_kernel(
    const int* __restrict__ mask,
    const float* __restrict__ w_tag, const float* __restrict__ b_tag,
    float* __restrict__ out)
{
    int s = blockIdx.x;
    int tid = threadIdx.x;
    int lo = (s == 0) ? 0 : mask[s - 1];
    int hi = (s == NSEG - 1) ? TT : mask[s];

    if (lo >= hi) {
        if (tid < TAGS) out[s * TAGS + tid] = b_tag[tid];
        return;
    }

    __shared__ float red[256];
    __shared__ float e_sm[256];
    __shared__ float ctx[256];

    float m = -3.4e38f;
    for (int i = lo + tid; i < hi; i += 256) m = fmaxf(m, g_att[i]);
    red[tid] = m; __syncthreads();
    for (int w = 128; w > 0; w >>= 1) {
        if (tid < w) red[tid] = fmaxf(red[tid], red[tid + w]);
        __syncthreads();
    }
    m = red[0]; __syncthreads();

    float z = 0.f;
    for (int i = lo + tid; i < hi; i += 256) z += __expf(g_att[i] - m);
    red[tid] = z; __syncthreads();
    for (int w = 128; w > 0; w >>= 1) {
        if (tid < w) red[tid] += red[tid + w];
        __syncthreads();
    }
    z = red[0]; __syncthreads();

    float acc = 0.f;
    for (int base = lo; base < hi; base += 256) {
        int i = base + tid;
        e_sm[tid] = (i < hi) ? __expf(g_att[i] - m) : 0.f;
        __syncthreads();
        int n = min(256, hi - base);
        for (int jx = 0; jx < n; jx++)
            acc = fmaf(g_hs[base + jx][tid], e_sm[jx], acc);
        __syncthreads();
    }
    ctx[tid] = acc / z;
    __syncthreads();

    if (tid < TAGS) {
        float rr = b_tag[tid];
        for (int d = 0; d < HID; d++) rr = fmaf(ctx[d], w_tag[tid * HID + d], rr);
        out[s * TAGS + tid] = rr;
    }
}

// ---------------------------------------------------------------------------
extern "C" void kernel_launch(void* const* d_in, const int* in_sizes, int n_in,
                              void* d_out, int out_size)
{
    const float* sentence = (const float*)d_in[0];
    const float* h0       = (const float*)d_in[1];
    const float* c0       = (const float*)d_in[2];
    const float* w_ih_f   = (const float*)d_in[3];
    const float* w_hh_f   = (const float*)d_in[4];
    const float* b_ih_f   = (const float*)d_in[5];
    const float* b_hh_f   = (const float*)d_in[6];
    const float* w_ih_b   = (const float*)d_in[7];
    const float* w_hh_b   = (const float*)d_in[8];
    const float* b_ih_b   = (const float*)d_in[9];
    const float* b_hh_b   = (const float*)d_in[10];
    const float* w_omega  = (const float*)d_in[11];
    const float* u_omega  = (const float*)d_in[12];
    const float* w_tag    = (const float*)d_in[13];
    const float* b_tag    = (const float*)d_in[14];
    const int*   doc_mask = (const int*)d_in[15];
    float* out = (float*)d_out;

    cudaFuncSetAttribute(attn_kernel, cudaFuncAttributeMaxDynamicSharedMemorySize, ATTN_SMEM);

    dim3 ggrid(TT / 64, G4 / 64, 2);
    gemm_pre_kernel<<<ggrid, 256>>>(sentence, w_ih_f, b_ih_f, b_hh_f,
                                    w_ih_b, b_ih_b, b_hh_b);
    lstm_kernel<<<4, 256>>>(w_hh_f, w_hh_b, h0, c0);
    attn_kernel<<<TT / 64, 256, ATTN_SMEM>>>(w_omega, u_omega);
    seg_pool_kernel<<<NSEG, 256>>>(doc_mask, w_tag, b_tag, out);
}

// round 15
// speedup vs baseline: 3.6468x; 2.3133x over previous
#include <cuda_runtime.h>
#include <math.h>
#include <stdint.h>

// Problem constants
#define TT   131072   // tokens
#define D_IN 256      // input dim
#define HH   128      // per-direction hidden
#define G4   512      // 4*HH gate rows
#define HID  256      // bidirectional hidden
#define TAGS 10
#define NSEG 1024

// Scratch (device globals — no allocation allowed in kernel_launch)
__device__ float g_pre[2][TT][G4];   // pre-activations per direction (original token order)
__device__ float g_hs[TT][HID];      // [hf | hb] concatenated
__device__ float g_att[TT];          // attention logits

// Fast activations: __expf (EX2) + __fdividef (~2 ulp). Inf-safe saturation.
__device__ __forceinline__ float fsigmoid(float x) {
    return __fdividef(1.0f, 1.0f + __expf(-x));
}
__device__ __forceinline__ float ftanh(float x) {
    return 1.0f - __fdividef(2.0f, __expf(2.0f * x) + 1.0f);
}
// Accurate tanh for the (non-recurrent) attention path
__device__ __forceinline__ float tanh_acc(float x) {
    return 1.0f - 2.0f / (__expf(2.0f * x) + 1.0f);
}

// Packed dual-FMA (Blackwell f32x2). acc.{lo,hi} += a.{lo,hi} * b.{lo,hi}
__device__ __forceinline__ void ffma2(unsigned long long& acc,
                                      unsigned long long a,
                                      unsigned long long b) {
    asm("fma.rn.f32x2 %0, %1, %2, %0;" : "+l"(acc) : "l"(a), "l"(b));
}

__device__ __forceinline__ uint32_t smem_u32(const void* p) {
    uint32_t a;
    asm("{ .reg .u64 t; cvta.to.shared.u64 t, %1; cvt.u32.u64 %0, t; }"
        : "=r"(a) : "l"(p));
    return a;
}

#define CB_ARRIVE() asm volatile("barrier.cluster.arrive.aligned;" ::: "memory")
#define CB_WAIT()   asm volatile("barrier.cluster.wait.aligned;" ::: "memory")

// ---------------------------------------------------------------------------
// Kernel A: pre[dir][t][g] = x[t] . w_ih[g] + b_ih[g] + b_hh[g]
// ---------------------------------------------------------------------------
__global__ __launch_bounds__(256) void gemm_pre_kernel(
    const float* __restrict__ x,
    const float* __restrict__ wf, const float* __restrict__ bif, const float* __restrict__ bhf,
    const float* __restrict__ wb, const float* __restrict__ bib, const float* __restrict__ bhb)
{
    int dir = blockIdx.z;
    const float* w  = dir ? wb  : wf;
    const float* b1 = dir ? bib : bif;
    const float* b2 = dir ? bhb : bhf;
    float* out = &g_pre[dir][0][0];

    int tok0 = blockIdx.x * 64;
    int g0   = blockIdx.y * 64;

    __shared__ float xs[16][64];
    __shared__ float wsm[16][64];

    int tid = threadIdx.x;
    int tx = tid & 15;
    int ty = tid >> 4;

    float acc[4][4];
#pragma unroll
    for (int i = 0; i < 4; i++)
#pragma unroll
        for (int j = 0; j < 4; j++) acc[i][j] = 0.f;

    int lr = tid >> 2;
    int lc = (tid & 3) * 4;

    for (int kk = 0; kk < D_IN; kk += 16) {
        float4 xv = *(const float4*)(x + (size_t)(tok0 + lr) * D_IN + kk + lc);
        float4 wv = *(const float4*)(w + (size_t)(g0  + lr) * D_IN + kk + lc);
        xs[lc + 0][lr] = xv.x; xs[lc + 1][lr] = xv.y; xs[lc + 2][lr] = xv.z; xs[lc + 3][lr] = xv.w;
        wsm[lc + 0][lr] = wv.x; wsm[lc + 1][lr] = wv.y; wsm[lc + 2][lr] = wv.z; wsm[lc + 3][lr] = wv.w;
        __syncthreads();
#pragma unroll
        for (int k = 0; k < 16; k++) {
            float4 a = *(const float4*)&xs[k][ty * 4];
            float4 b = *(const float4*)&wsm[k][tx * 4];
            float av[4] = {a.x, a.y, a.z, a.w};
            float bv[4] = {b.x, b.y, b.z, b.w};
#pragma unroll
            for (int i = 0; i < 4; i++)
#pragma unroll
                for (int j = 0; j < 4; j++)
                    acc[i][j] = fmaf(av[i], bv[j], acc[i][j]);
        }
        __syncthreads();
    }

    int g = g0 + tx * 4;
    float bb0 = b1[g + 0] + b2[g + 0];
    float bb1 = b1[g + 1] + b2[g + 1];
    float bb2 = b1[g + 2] + b2[g + 2];
    float bb3 = b1[g + 3] + b2[g + 3];
#pragma unroll
    for (int i = 0; i < 4; i++) {
        int tok = tok0 + ty * 4 + i;
        float4 o;
        o.x = acc[i][0] + bb0;
        o.y = acc[i][1] + bb1;
        o.z = acc[i][2] + bb2;
        o.w = acc[i][3] + bb3;
        *(float4*)(out + (size_t)tok * G4 + g) = o;
    }
}

// ---------------------------------------------------------------------------
// Kernel B: sequential LSTM, 4-CTA cluster per direction, H-INDEX split with
// warp-local gate gather. One fused barrier.cluster per step; NO __syncthreads
// in the loop; activations run BEFORE the barrier (off the post-barrier path).
//
// grid = 8 CTAs, cluster dims 4: {0..3}=fwd, {4..7}=bwd.
// rank owns h indices j in [rank*32, rank*32+32) with ALL 4 gates:
//   128 threads; warp w (0..3), lane: gate=lane>>3, jj=lane&7,
//   j = rank*32 + 8w + jj, row r = gate*128 + j (thread owns FULL row:
//   128 cols = 64 u64 regs; ~170 regs/thread at 128 thr -> no spill).
// Per step:
//   v = pre[r] + W_row . hbuf[p]        (4 independent 16-deep f32x2 chains)
//   3 shuffles gather f,g,o into i-lanes (warp-local)
//   lanes<8: act -> c,h for own j; store h -> local hbuf[np][j] and the same
//     slot in the 3 peers (st.shared::cluster); write own g_hs slice
//   CB_ARRIVE + CB_WAIT (fused):
//     - my arrive releases my remote h stores; my wait acquires peers' stores
//     - superset of __syncthreads -> local hbuf[np] writes also ordered
// WAR on hbuf (double-buffered): peer writes to buffer A at step u+2 are
// po-after its wait(u+1), which needs my arrive(u+1), po-after my step-u+1
// reads of A. Mechanisms identical to R10 (proven); only partition + payload
// (32 h/CTA vs 512 gate sums) and chain order changed.
// ---------------------------------------------------------------------------
__global__ __launch_bounds__(128, 1) __cluster_dims__(4, 1, 1)
void lstm_kernel(
    const float* __restrict__ w_hh_f, const float* __restrict__ w_hh_b,
    const float* __restrict__ h0, const float* __restrict__ c0)
{
    __shared__ __align__(16) float hbuf[2][HH];

    int dir       = blockIdx.x >> 2;
    uint32_t rank = blockIdx.x & 3u;
    int t    = threadIdx.x;
    int w    = t >> 5;
    int lane = t & 31;
    int jj   = lane & 7;
    int j    = (int)rank * 32 + 8 * w + jj;   // h index this thread's group owns
    int gate = lane >> 3;
    int r    = gate * HH + j;                 // full gate row this thread owns

    const float* W = dir ? w_hh_b : w_hh_f;
    const ulonglong2* Wrow = (const ulonglong2*)(W + (size_t)r * HH);

    // Full row of weights in registers: 128 cols = 64 packed f32 pairs
    unsigned long long wp[64];
#pragma unroll
    for (int i = 0; i < 32; i++) {
        ulonglong2 v = Wrow[i];
        wp[2 * i]     = v.x;
        wp[2 * i + 1] = v.y;
    }

    // init h (each CTA loads the FULL h0 itself), c for producer lanes
    hbuf[0][t] = h0[dir * HH + t];
    float c_reg = 0.f;
    if (lane < 8) c_reg = c0[dir * HH + j];
    __syncthreads();

    // Peer hbuf addresses for my h slot (3 peers, computed once)
    uint32_t l_hbuf = smem_u32(&hbuf[0][0]);
    uint32_t slot = (uint32_t)j * 4u;          // + np*HH*4
    uint32_t ph[3];
    {
        int n = 0;
#pragma unroll
        for (uint32_t q = 0; q < 4; q++) {
            if (q != rank) {
                uint32_t b;
                asm("mapa.shared::cluster.u32 %0, %1, %2;" : "=r"(b) : "r"(l_hbuf), "r"(q));
                ph[n++] = b + slot;
            }
        }
    }

    // cluster residency + hbuf[0] ready everywhere before any remote store
    CB_ARRIVE(); CB_WAIT();

    const float* P = &g_pre[dir][0][0];
    int row    = dir ? (TT - 1) : 0;
    int stride = dir ? -1 : 1;

    // 2-deep prefetch of this row's pre-activation stream
    float pf0, pf1;
    {
        int r1 = row + stride;
        int r1c = r1 < 0 ? 0 : (r1 >= TT ? TT - 1 : r1);
        pf0 = __ldg(P + (size_t)row * G4 + r);
        pf1 = __ldg(P + (size_t)r1c * G4 + r);
    }

    int p = 0;

    for (int step = 0; step < TT; step++) {
        float pre_cur = pf0;
        pf0 = pf1;
        {
            int rr = row + 2 * stride;
            int rc = rr < 0 ? 0 : (rr >= TT ? TT - 1 : rr);
            pf1 = __ldg(P + (size_t)rc * G4 + r);
        }

        // Full-row matvec over complete local h: 4 independent 16-deep chains
        const ulonglong2* hp = (const ulonglong2*)&hbuf[p][0];
        unsigned long long a0, a1, a2, a3;
        asm("mov.b64 %0, {%1,%2};" : "=l"(a0) : "f"(pre_cur), "f"(0.0f));
        asm("mov.b64 %0, {%1,%2};" : "=l"(a1) : "f"(0.0f), "f"(0.0f));
        a2 = a1; a3 = a1;
#pragma unroll
        for (int i = 0; i < 32; i += 2) {
            ulonglong2 h0v = hp[i];
            ulonglong2 h1v = hp[i + 1];
            ffma2(a0, wp[2 * i],     h0v.x);
            ffma2(a1, wp[2 * i + 1], h0v.y);
            ffma2(a2, wp[2 * i + 2], h1v.x);
            ffma2(a3, wp[2 * i + 3], h1v.y);
        }
        float s0, s1, s2, s3, s4, s5, s6, s7;
        asm("mov.b64 {%0,%1}, %2;" : "=f"(s0), "=f"(s1) : "l"(a0));
        asm("mov.b64 {%0,%1}, %2;" : "=f"(s2), "=f"(s3) : "l"(a1));
        asm("mov.b64 {%0,%1}, %2;" : "=f"(s4), "=f"(s5) : "l"(a2));
        asm("mov.b64 {%0,%1}, %2;" : "=f"(s6), "=f"(s7) : "l"(a3));
        float v = ((s0 + s1) + (s2 + s3)) + ((s4 + s5) + (s6 + s7));

        // Warp-local gate gather: f,g,o into the i-gate lanes (0..7)
        float gf = __shfl_sync(0xffffffffu, v, 8 + jj);
        float gg = __shfl_sync(0xffffffffu, v, 16 + jj);
        float go = __shfl_sync(0xffffffffu, v, 24 + jj);

        int np = p ^ 1;
        if (lane < 8) {
            float iv = fsigmoid(v);
            float fv = fsigmoid(gf);
            float gv = ftanh(gg);
            float ov = fsigmoid(go);
            c_reg = fv * c_reg + iv * gv;
            float hv = ov * ftanh(c_reg);
            hbuf[np][j] = hv;
            const uint32_t no = (uint32_t)(np * HH * 4);
            asm volatile("st.shared::cluster.f32 [%0], %1;" :: "r"(ph[0] + no), "f"(hv) : "memory");
            asm volatile("st.shared::cluster.f32 [%0], %1;" :: "r"(ph[1] + no), "f"(hv) : "memory");
            asm volatile("st.shared::cluster.f32 [%0], %1;" :: "r"(ph[2] + no), "f"(hv) : "memory");
            g_hs[row][HH * dir + j] = hv;
        }

        // One fused cluster barrier: releases my h stores, acquires peers',
        // and (superset of __syncthreads) orders local hbuf[np] writes.
        CB_ARRIVE(); CB_WAIT();

        p = np;
        row += stride;
    }

    // no CTA may exit while peers can still touch its smem
    CB_ARRIVE(); CB_WAIT();
}

// ---------------------------------------------------------------------------
// Kernel C: att[t] = sum_d tanh( (x @ w_omega)[t,d] ) * u_omega[d]
// ---------------------------------------------------------------------------
#define ATTN_SMEM ((64 * HID + 16 * 257) * 4)

__global__ __launch_bounds__(256) void attn_kernel(
    const float* __restrict__ w_omega, const float* __restrict__ u_omega)
{
    extern __shared__ float smc[];
    float* xs  = smc;
    float* red = smc + 64 * HID;

    int tid  = threadIdx.x;
    int tok0 = blockIdx.x * 64;

    const float4* src = (const float4*)&g_hs[tok0][0];
    float4* dst = (float4*)xs;
    for (int idx = tid; idx < 64 * HID / 4; idx += 256) dst[idx] = src[idx];
    __syncthreads();

    float uo = u_omega[tid];

    for (int c = 0; c < 4; c++) {
        float acc[16];
#pragma unroll
        for (int t = 0; t < 16; t++) acc[t] = 0.f;
        const float* xbase = xs + (c * 16) * HID;

        for (int k = 0; k < HID; k += 4) {
            float w0 = __ldg(w_omega + (k + 0) * HID + tid);
            float w1 = __ldg(w_omega + (k + 1) * HID + tid);
            float w2 = __ldg(w_omega + (k + 2) * HID + tid);
            float w3 = __ldg(w_omega + (k + 3) * HID + tid);
#pragma unroll
            for (int t = 0; t < 16; t++) {
                float4 xv = *(const float4*)(xbase + t * HID + k);
                acc[t] = fmaf(xv.x, w0,
                         fmaf(xv.y, w1,
                         fmaf(xv.z, w2,
                         fmaf(xv.w, w3, acc[t]))));
            }
        }
#pragma unroll
        for (int t = 0; t < 16; t++)
            red[t * 257 + tid] = tanh_acc(acc[t]) * uo;
        __syncthreads();
        if (tid < 16) {
            float s = 0.f;
            for (int jx = 0; jx < HID; jx++) s += red[tid * 257 + jx];
            g_att[tok0 + c * 16 + tid] = s;
        }
        __syncthreads();
    }
}

// ---------------------------------------------------------------------------
// Kernel D: per-segment softmax pooling + tag projection
// ---------------------------------------------------------------------------
__global__ __launch_bounds__(256) void seg_pool_kernel(
    const int* __restrict__ mask,
    const float* __restrict__ w_tag, const float* __restrict__ b_tag,
    float* __restrict__ out)
{
    int s = blockIdx.x;
    int tid = threadIdx.x;
    int lo = (s == 0) ? 0 : mask[s - 1];
    int hi = (s == NSEG - 1) ? TT : mask[s];

    if (lo >= hi) {
        if (tid < TAGS) out[s * TAGS + tid] = b_tag[tid];
        return;
    }

    __shared__ float red[256];
    __shared__ float e_sm[256];
    __shared__ float ctx[256];

    float m = -3.4e38f;
    for (int i = lo + tid; i < hi; i += 256) m = fmaxf(m, g_att[i]);
    red[tid] = m; __syncthreads();
    for (int w = 128; w > 0; w >>= 1) {
        if (tid < w) red[tid] = fmaxf(red[tid], red[tid + w]);
        __syncthreads();
    }
    m = red[0]; __syncthreads();

    float z = 0.f;
    for (int i = lo + tid; i < hi; i += 256) z += __expf(g_att[i] - m);
    red[tid] = z; __syncthreads();
    for (int w = 128; w > 0; w >>= 1) {
        if (tid < w) red[tid] += red[tid + w];
        __syncthreads();
    }
    z = red[0]; __syncthreads();

    float acc = 0.f;
    for (int base = lo; base < hi; base += 256) {
        int i = base + tid;
        e_sm[tid] = (i < hi) ? __expf(g_att[i] - m) : 0.f;
        __syncthreads();
        int n = min(256, hi - base);
        for (int jx = 0; jx < n; jx++)
            acc = fmaf(g_hs[base + jx][tid], e_sm[jx], acc);
        __syncthreads();
    }
    ctx[tid] = acc / z;
    __syncthreads();

    if (tid < TAGS) {
        float rr = b_tag[tid];
        for (int d = 0; d < HID; d++) rr = fmaf(ctx[d], w_tag[tid * HID + d], rr);
        out[s * TAGS + tid] = rr;
    }
}

// ---------------------------------------------------------------------------
extern "C" void kernel_launch(void* const* d_in, const int* in_sizes, int n_in,
                              void* d_out, int out_size)
{
    const float* sentence = (const float*)d_in[0];
    const float* h0       = (const float*)d_in[1];
    const float* c0       = (const float*)d_in[2];
    const float* w_ih_f   = (const float*)d_in[3];
    const float* w_hh_f   = (const float*)d_in[4];
    const float* b_ih_f   = (const float*)d_in[5];
    const float* b_hh_f   = (const float*)d_in[6];
    const float* w_ih_b   = (const float*)d_in[7];
    const float* w_hh_b   = (const float*)d_in[8];
    const float* b_ih_b   = (const float*)d_in[9];
    const float* b_hh_b   = (const float*)d_in[10];
    const float* w_omega  = (const float*)d_in[11];
    const float* u_omega  = (const float*)d_in[12];
    const float* w_tag    = (const float*)d_in[13];
    const float* b_tag    = (const float*)d_in[14];
    const int*   doc_mask = (const int*)d_in[15];
    float* out = (float*)d_out;

    cudaFuncSetAttribute(attn_kernel, cudaFuncAttributeMaxDynamicSharedMemorySize, ATTN_SMEM);

    dim3 ggrid(TT / 64, G4 / 64, 2);
    gemm_pre_kernel<<<ggrid, 256>>>(sentence, w_ih_f, b_ih_f, b_hh_f,
                                    w_ih_b, b_ih_b, b_hh_b);
    lstm_kernel<<<8, 128>>>(w_hh_f, w_hh_b, h0, c0);
    attn_kernel<<<TT / 64, 256, ATTN_SMEM>>>(w_omega, u_omega);
    seg_pool_kernel<<<NSEG, 256>>>(doc_mask, w_tag, b_tag, out);
}